// round 1
// baseline (speedup 1.0000x reference)
#include <cuda_runtime.h>
#include <math.h>

// Problem constants (B=2, C=128, H=64, W=64)
#define NPIX 8192
#define CDIM 128
#define HW   4096
#define CHW  524288
#define NCLS 4
#define TILE 128
#define KC   32

#define INV_TAU 14.2857142857142857f   // 1/0.07

// ---------------- scratch (device globals; no allocation allowed) -------------
__device__ float gNT[NPIX * CDIM];   // normalized target rows  (N,128)
__device__ float gNI[NPIX * CDIM];   // normalized input rows   (N,128)
__device__ float gS[NCLS * NPIX];    // per-class column sums of exp(sim/tau)
__device__ float gPartial[32];       // block partial loss sums

// ---------------- zero gS ----------------------------------------------------
__global__ void zero_kernel() {
    int i = blockIdx.x * 256 + threadIdx.x;
    if (i < NCLS * NPIX) gS[i] = 0.0f;
}

// ---------------- normalize + transpose --------------------------------------
// One block handles 32 consecutive pixels (same batch since 4096 % 32 == 0).
// Reads (B,C,H,W) coalesced along hw, writes (N,C) coalesced along C.
__global__ void norm_kernel(const float* __restrict__ src, int which) {
    __shared__ float tile[CDIM][33];
    __shared__ float part[8][32];
    __shared__ float inv[32];

    float* dst = which ? gNT : gNI;

    const int tx = threadIdx.x;   // 0..31  pixel within group
    const int ty = threadIdx.y;   // 0..7   channel stride
    const int p0 = blockIdx.x * 32;
    const int b  = p0 >> 12;          // /4096
    const int hw = p0 & 4095;

    const float* base = src + (size_t)b * CHW + hw + tx;
    float ps = 0.0f;
    #pragma unroll
    for (int c = ty; c < CDIM; c += 8) {
        float v = base[c * HW];
        tile[c][tx] = v;
        ps += v * v;
    }
    part[ty][tx] = ps;
    __syncthreads();
    if (ty == 0) {
        float s = 0.0f;
        #pragma unroll
        for (int i = 0; i < 8; i++) s += part[i][tx];
        inv[tx] = rsqrtf(fmaxf(s, 1e-24f));
    }
    __syncthreads();

    const int tid = ty * 32 + tx;
    #pragma unroll
    for (int idx = tid; idx < 32 * CDIM; idx += 256) {
        int pix = idx >> 7;
        int c   = idx & 127;
        dst[(size_t)(p0 + pix) * CDIM + c] = tile[c][pix] * inv[pix];
    }
}

// ---------------- fused GEMM + exp + 4-class column reduce --------------------
// CTA tile 128x128, 256 threads, 8x8 micro-tile per thread.
// rows a = target pixels (class pt[a]), cols b = input pixels.
__global__ __launch_bounds__(256, 2)
void gemm_kernel(const int* __restrict__ ptSeg) {
    __shared__ float As[KC][132];   // As[k][row]  (target rows)
    __shared__ float Bs[KC][132];   // Bs[k][col]  (input rows)

    const int tid = threadIdx.x;
    const int ty  = tid >> 4;       // 0..15
    const int tx  = tid & 15;       // 0..15
    const int rowBlk = blockIdx.y * TILE;
    const int colBlk = blockIdx.x * TILE;

    float acc[8][8];
    #pragma unroll
    for (int i = 0; i < 8; i++)
        #pragma unroll
        for (int j = 0; j < 8; j++) acc[i][j] = 0.0f;

    int cls[8];
    #pragma unroll
    for (int i = 0; i < 8; i++) cls[i] = ptSeg[rowBlk + ty * 8 + i];

    #pragma unroll
    for (int kc = 0; kc < CDIM; kc += KC) {
        // stage: each thread moves 4 float4 from each matrix
        float4 av[4], bv[4];
        #pragma unroll
        for (int j = 0; j < 4; j++) {
            int i  = tid + 256 * j;
            int r  = i >> 3;        // 0..127 row within tile
            int k4 = i & 7;         // float4 index within 32-k chunk
            av[j] = *(const float4*)(gNT + (size_t)(rowBlk + r) * CDIM + kc + k4 * 4);
            bv[j] = *(const float4*)(gNI + (size_t)(colBlk + r) * CDIM + kc + k4 * 4);
        }
        if (kc) __syncthreads();
        #pragma unroll
        for (int j = 0; j < 4; j++) {
            int i  = tid + 256 * j;
            int r  = i >> 3;
            int k4 = i & 7;
            As[k4 * 4 + 0][r] = av[j].x; As[k4 * 4 + 1][r] = av[j].y;
            As[k4 * 4 + 2][r] = av[j].z; As[k4 * 4 + 3][r] = av[j].w;
            Bs[k4 * 4 + 0][r] = bv[j].x; Bs[k4 * 4 + 1][r] = bv[j].y;
            Bs[k4 * 4 + 2][r] = bv[j].z; Bs[k4 * 4 + 3][r] = bv[j].w;
        }
        __syncthreads();

        #pragma unroll
        for (int k = 0; k < KC; k++) {
            float a[8], b[8];
            *(float4*)(a)     = *(const float4*)&As[k][ty * 8];
            *(float4*)(a + 4) = *(const float4*)&As[k][ty * 8 + 4];
            *(float4*)(b)     = *(const float4*)&Bs[k][tx * 8];
            *(float4*)(b + 4) = *(const float4*)&Bs[k][tx * 8 + 4];
            #pragma unroll
            for (int i = 0; i < 8; i++)
                #pragma unroll
                for (int j = 0; j < 8; j++)
                    acc[i][j] = fmaf(a[i], b[j], acc[i][j]);
        }
    }
    __syncthreads();

    // epilogue: exp + per-class column sums via shared memory
    float* sRed = &As[0][0];   // reuse: NCLS * 132 floats
    for (int i = tid; i < NCLS * 132; i += 256) sRed[i] = 0.0f;
    __syncthreads();

    #pragma unroll
    for (int j = 0; j < 8; j++) {
        float s0 = 0.f, s1 = 0.f, s2 = 0.f, s3 = 0.f;
        #pragma unroll
        for (int i = 0; i < 8; i++) {
            float e = __expf(acc[i][j] * INV_TAU);
            s0 += (cls[i] == 0) ? e : 0.f;
            s1 += (cls[i] == 1) ? e : 0.f;
            s2 += (cls[i] == 2) ? e : 0.f;
            s3 += (cls[i] == 3) ? e : 0.f;
        }
        int c = tx * 8 + j;
        atomicAdd(&sRed[0 * 132 + c], s0);
        atomicAdd(&sRed[1 * 132 + c], s1);
        atomicAdd(&sRed[2 * 132 + c], s2);
        atomicAdd(&sRed[3 * 132 + c], s3);
    }
    __syncthreads();

    for (int i = tid; i < NCLS * TILE; i += 256) {
        int cc = i >> 7;
        int c  = i & 127;
        atomicAdd(&gS[cc * NPIX + colBlk + c], sRed[cc * 132 + c]);
    }
}

// ---------------- final loss --------------------------------------------------
__global__ void loss_part_kernel(const int* __restrict__ piSeg) {
    __shared__ float red[256];
    const int b = blockIdx.x * 256 + threadIdx.x;
    int p = piSeg[b];
    float nom = gS[p * NPIX + b];
    float den = gS[b] + gS[NPIX + b] + gS[2 * NPIX + b] + gS[3 * NPIX + b];
    red[threadIdx.x] = -logf(nom / (den + 1e-8f));
    __syncthreads();
    for (int s = 128; s > 0; s >>= 1) {
        if (threadIdx.x < s) red[threadIdx.x] += red[threadIdx.x + s];
        __syncthreads();
    }
    if (threadIdx.x == 0) gPartial[blockIdx.x] = red[0];
}

__global__ void loss_final_kernel(float* __restrict__ out) {
    float v = gPartial[threadIdx.x];
    #pragma unroll
    for (int o = 16; o; o >>= 1) v += __shfl_down_sync(0xffffffffu, v, o);
    if (threadIdx.x == 0) out[0] = v * (1.0f / (float)NPIX);
}

// ---------------- launch ------------------------------------------------------
extern "C" void kernel_launch(void* const* d_in, const int* in_sizes, int n_in,
                              void* d_out, int out_size) {
    const float* input  = (const float*)d_in[0];
    const float* target = (const float*)d_in[1];
    const int*   iseg   = (const int*)d_in[2];
    const int*   tseg   = (const int*)d_in[3];
    float* out = (float*)d_out;

    zero_kernel<<<(NCLS * NPIX + 255) / 256, 256>>>();
    dim3 nb(32, 8);
    norm_kernel<<<NPIX / 32, nb>>>(target, 1);
    norm_kernel<<<NPIX / 32, nb>>>(input, 0);

    dim3 grid(NPIX / TILE, NPIX / TILE);
    gemm_kernel<<<grid, 256>>>(tseg);

    loss_part_kernel<<<NPIX / 256, 256>>>(iseg);
    loss_final_kernel<<<1, 32>>>(out);
}

// round 3
// speedup vs baseline: 2.9730x; 2.9730x over previous
#include <cuda_runtime.h>
#include <cuda_bf16.h>
#include <cstdint>
#include <math.h>

// Problem constants (B=2, C=128, H=64, W=64)
#define NPIX 8192
#define CDIM 128
#define HW   4096
#define CHW  524288
#define NCLS 4
#define K2   256          // stored K: [hi(128) | lo(128)] bf16
#define INV_TAU 14.285714285714286f

// ---------------- scratch (device globals; no allocation allowed) -------------
__device__ __nv_bfloat16 gA[NPIX * K2];  // input rows  [hi|lo]  (rows of D)
__device__ __nv_bfloat16 gB[NPIX * K2];  // target rows [hi|lo]  (cols of D)
__device__ float gS[NCLS * NPIX];        // per-class sums of exp(sim/tau) per input pixel
__device__ float gPartial[32];

// dynamic smem: [0,65536) A stage, [65536,131072) B stage, reused as D 128x132 f32
// cls ints at 131072
#define SM_TOTAL (131072 + 512)

// ---------------- helpers -----------------------------------------------------
__device__ __forceinline__ uint32_t smem_u32(const void* p) {
    uint32_t a;
    asm("{ .reg .u64 t; cvta.to.shared.u64 t, %1; cvt.u32.u64 %0, t; }"
        : "=r"(a) : "l"(p));
    return a;
}

__device__ __forceinline__ void ldsm_x4(uint32_t& r0, uint32_t& r1, uint32_t& r2,
                                        uint32_t& r3, uint32_t a) {
    asm volatile("ldmatrix.sync.aligned.m8n8.x4.shared.b16 {%0,%1,%2,%3}, [%4];"
                 : "=r"(r0), "=r"(r1), "=r"(r2), "=r"(r3) : "r"(a));
}

__device__ __forceinline__ void mma16816(float* d, const uint32_t* a, const uint32_t* b) {
    asm volatile(
        "mma.sync.aligned.m16n8k16.row.col.f32.bf16.bf16.f32 "
        "{%0,%1,%2,%3}, {%4,%5,%6,%7}, {%8,%9}, {%0,%1,%2,%3};"
        : "+f"(d[0]), "+f"(d[1]), "+f"(d[2]), "+f"(d[3])
        : "r"(a[0]), "r"(a[1]), "r"(a[2]), "r"(a[3]), "r"(b[0]), "r"(b[1]));
}

// ---------------- zero gS ------------------------------------------------------
__global__ void zero_kernel() {
    int i = blockIdx.x * 256 + threadIdx.x;
    if (i < NCLS * NPIX) gS[i] = 0.0f;
}

// ---------------- normalize + transpose + hi/lo split --------------------------
__global__ void norm_kernel(const float* __restrict__ src, int which) {
    __shared__ float tile[CDIM][33];
    __shared__ float part[8][32];
    __shared__ float inv[32];

    __nv_bfloat16* dst = which ? gB : gA;   // 1 = target, 0 = input

    const int tx = threadIdx.x;   // 0..31 pixel in group
    const int ty = threadIdx.y;   // 0..7  channel stride
    const int p0 = blockIdx.x * 32;
    const int b  = p0 >> 12;
    const int hw = p0 & 4095;

    const float* base = src + (size_t)b * CHW + hw + tx;
    float ps = 0.0f;
    #pragma unroll
    for (int c = ty; c < CDIM; c += 8) {
        float v = base[c * HW];
        tile[c][tx] = v;
        ps += v * v;
    }
    part[ty][tx] = ps;
    __syncthreads();
    if (ty == 0) {
        float s = 0.0f;
        #pragma unroll
        for (int i = 0; i < 8; i++) s += part[i][tx];
        inv[tx] = rsqrtf(fmaxf(s, 1e-24f));
    }
    __syncthreads();

    const int tid = ty * 32 + tx;
    #pragma unroll
    for (int idx = tid; idx < 32 * CDIM; idx += 256) {
        int pix = idx >> 7;
        int c   = idx & 127;
        float v = tile[c][pix] * inv[pix];
        __nv_bfloat16 h = __float2bfloat16(v);
        __nv_bfloat16 l = __float2bfloat16(v - __bfloat162float(h));
        size_t o = (size_t)(p0 + pix) * K2 + c;
        dst[o] = h;
        dst[o + CDIM] = l;
    }
}

// ---------------- HMMA GEMM + exp + 4-class column reduce ----------------------
// D[b, a] = input_row(b) . target_row(a) over K=256 ([hi|lo] both sides)
// rows (M) = input pixels from blockIdx.x, cols (N) = target pixels from blockIdx.y
__global__ __launch_bounds__(256, 1)
void gemm_kernel(const int* __restrict__ tseg) {
    extern __shared__ char smem[];
    float* Dsm = (float*)smem;                 // 128 x 132 fp32 (reuses staging)
    int*   cls = (int*)(smem + 131072);        // 128 target classes

    const int tid  = threadIdx.x;
    const int wid  = tid >> 5;
    const int lane = tid & 31;

    if (tid < 128) cls[tid] = tseg[blockIdx.y * 128 + tid];

    // ---- stage A (input rows) and B (target rows): 128 rows x 512B, swizzled
    const uint4* ga4 = (const uint4*)gA;
    const uint4* gb4 = (const uint4*)gB;
    #pragma unroll
    for (int j = 0; j < 16; j++) {
        int i = tid + j * 256;          // 0..4095
        int r = i >> 5;                 // row 0..127
        int c = i & 31;                 // 16B chunk 0..31
        int sw = c ^ (r & 7);
        *(uint4*)(smem + r * 512 + sw * 16) =
            ga4[(size_t)(blockIdx.x * 128 + r) * 32 + c];
        *(uint4*)(smem + 65536 + r * 512 + sw * 16) =
            gb4[(size_t)(blockIdx.y * 128 + r) * 32 + c];
    }
    __syncthreads();

    // ---- warp tiling: 2 x 4 warps, warp tile 64 rows x 32 cols
    const int wm = wid >> 2;            // 0..1
    const int wn = wid & 3;             // 0..3
    const uint32_t sbase = smem_u32(smem);

    float acc[4][4][4];
    #pragma unroll
    for (int mt = 0; mt < 4; mt++)
        #pragma unroll
        for (int nt = 0; nt < 4; nt++)
            #pragma unroll
            for (int q = 0; q < 4; q++) acc[mt][nt][q] = 0.0f;

    const int ar = wm * 64 + (lane & 15);            // A row per lane
    const int ah = lane >> 4;                        // A k-half (16B) select
    const int bc = wn * 32 + (lane & 7) + ((lane >> 4) << 3);  // B col per lane
    const int bh = (lane >> 3) & 1;                  // B k-half select

    #pragma unroll
    for (int kk = 0; kk < 16; kk++) {
        uint32_t a[4][4];
        #pragma unroll
        for (int mt = 0; mt < 4; mt++) {
            int r = ar + mt * 16;
            int c = kk * 2 + ah;
            uint32_t addr = sbase + r * 512 + ((c ^ (r & 7)) << 4);
            ldsm_x4(a[mt][0], a[mt][1], a[mt][2], a[mt][3], addr);
        }
        uint32_t b[4][2];
        #pragma unroll
        for (int p = 0; p < 2; p++) {
            int c0 = bc + p * 16;
            int c = kk * 2 + bh;
            uint32_t addr = sbase + 65536 + c0 * 512 + ((c ^ (c0 & 7)) << 4);
            ldsm_x4(b[2 * p][0], b[2 * p][1], b[2 * p + 1][0], b[2 * p + 1][1], addr);
        }
        #pragma unroll
        for (int mt = 0; mt < 4; mt++)
            #pragma unroll
            for (int nt = 0; nt < 4; nt++)
                mma16816(acc[mt][nt], a[mt], b[nt]);
    }
    __syncthreads();   // staging region dead; reuse as D

    // ---- write D fragments to smem
    #pragma unroll
    for (int mt = 0; mt < 4; mt++)
        #pragma unroll
        for (int nt = 0; nt < 4; nt++) {
            int r0 = wm * 64 + mt * 16 + (lane >> 2);
            int c0 = wn * 32 + nt * 8 + (lane & 3) * 2;
            Dsm[r0 * 132 + c0]           = acc[mt][nt][0];
            Dsm[r0 * 132 + c0 + 1]       = acc[mt][nt][1];
            Dsm[(r0 + 8) * 132 + c0]     = acc[mt][nt][2];
            Dsm[(r0 + 8) * 132 + c0 + 1] = acc[mt][nt][3];
        }
    __syncthreads();

    // ---- exp + per-class sums along target dim; 2 threads per input row
    {
        const int row  = tid >> 1;
        const int half = tid & 1;
        const float* dr = Dsm + row * 132 + half * 64;
        const int*  cl  = cls + half * 64;
        float s0 = 0.f, s1 = 0.f, s2 = 0.f, s3 = 0.f;
        #pragma unroll
        for (int c = 0; c < 64; c++) {
            float e = __expf(dr[c] * INV_TAU);
            int k = cl[c];
            s0 += (k == 0) ? e : 0.f;
            s1 += (k == 1) ? e : 0.f;
            s2 += (k == 2) ? e : 0.f;
            s3 += (k == 3) ? e : 0.f;
        }
        s0 += __shfl_xor_sync(0xffffffffu, s0, 1);
        s1 += __shfl_xor_sync(0xffffffffu, s1, 1);
        s2 += __shfl_xor_sync(0xffffffffu, s2, 1);
        s3 += __shfl_xor_sync(0xffffffffu, s3, 1);
        if (half == 0) {
            int bg = blockIdx.x * 128 + row;
            atomicAdd(&gS[0 * NPIX + bg], s0);
            atomicAdd(&gS[1 * NPIX + bg], s1);
            atomicAdd(&gS[2 * NPIX + bg], s2);
            atomicAdd(&gS[3 * NPIX + bg], s3);
        }
    }
}

// ---------------- final loss ---------------------------------------------------
__global__ void loss_part_kernel(const int* __restrict__ piSeg) {
    __shared__ float red[256];
    const int b = blockIdx.x * 256 + threadIdx.x;
    int p = piSeg[b];
    float nom = gS[p * NPIX + b];
    float den = gS[b] + gS[NPIX + b] + gS[2 * NPIX + b] + gS[3 * NPIX + b];
    red[threadIdx.x] = -logf(nom / (den + 1e-8f));
    __syncthreads();
    for (int s = 128; s > 0; s >>= 1) {
        if (threadIdx.x < s) red[threadIdx.x] += red[threadIdx.x + s];
        __syncthreads();
    }
    if (threadIdx.x == 0) gPartial[blockIdx.x] = red[0];
}

__global__ void loss_final_kernel(float* __restrict__ out) {
    float v = gPartial[threadIdx.x];
    #pragma unroll
    for (int o = 16; o; o >>= 1) v += __shfl_down_sync(0xffffffffu, v, o);
    if (threadIdx.x == 0) out[0] = v * (1.0f / (float)NPIX);
}

// ---------------- launch -------------------------------------------------------
extern "C" void kernel_launch(void* const* d_in, const int* in_sizes, int n_in,
                              void* d_out, int out_size) {
    const float* input  = (const float*)d_in[0];
    const float* target = (const float*)d_in[1];
    const int*   iseg   = (const int*)d_in[2];
    const int*   tseg   = (const int*)d_in[3];
    float* out = (float*)d_out;

    cudaFuncSetAttribute(gemm_kernel, cudaFuncAttributeMaxDynamicSharedMemorySize, SM_TOTAL);

    zero_kernel<<<(NCLS * NPIX + 255) / 256, 256>>>();
    dim3 nb(32, 8);
    norm_kernel<<<NPIX / 32, nb>>>(input, 0);
    norm_kernel<<<NPIX / 32, nb>>>(target, 1);

    dim3 grid(NPIX / 128, NPIX / 128);
    gemm_kernel<<<grid, 256, SM_TOTAL>>>(tseg);

    loss_part_kernel<<<NPIX / 256, 256>>>(iseg);
    loss_final_kernel<<<1, 32>>>(out);
}

// round 4
// speedup vs baseline: 3.7145x; 1.2494x over previous
#include <cuda_runtime.h>
#include <cuda_bf16.h>
#include <cstdint>
#include <math.h>

// Problem constants (B=2, C=128, H=64, W=64)
#define NPIX 8192
#define CDIM 128
#define HW   4096
#define CHW  524288
#define NCLS 4
#define K2   256          // stored K: [hi(128) | lo(128)] bf16
#define INV_TAU 14.285714285714286f

// ---------------- scratch (device globals; no allocation allowed) -------------
__device__ __nv_bfloat16 gA[NPIX * K2];  // input rows  [hi|lo]  (rows of D)
__device__ __nv_bfloat16 gB[NPIX * K2];  // target rows [hi|lo]  (cols of D)
__device__ float gS[NCLS * NPIX];        // per-class sums of exp(sim/tau) per input pixel
__device__ float gPartial[32];

// dynamic smem: buf0 [0,32K) {A 16K | B 16K}, buf1 [32K,64K), cls @65536, sRed @66048
#define SM_CLS   65536
#define SM_RED   66048
#define SM_TOTAL (66048 + 2048)

// ---------------- helpers -----------------------------------------------------
__device__ __forceinline__ uint32_t smem_u32(const void* p) {
    uint32_t a;
    asm("{ .reg .u64 t; cvta.to.shared.u64 t, %1; cvt.u32.u64 %0, t; }"
        : "=r"(a) : "l"(p));
    return a;
}

__device__ __forceinline__ void ldsm_x4(uint32_t& r0, uint32_t& r1, uint32_t& r2,
                                        uint32_t& r3, uint32_t a) {
    asm volatile("ldmatrix.sync.aligned.m8n8.x4.shared.b16 {%0,%1,%2,%3}, [%4];"
                 : "=r"(r0), "=r"(r1), "=r"(r2), "=r"(r3) : "r"(a));
}

__device__ __forceinline__ void mma16816(float* d, const uint32_t* a, const uint32_t* b) {
    asm volatile(
        "mma.sync.aligned.m16n8k16.row.col.f32.bf16.bf16.f32 "
        "{%0,%1,%2,%3}, {%4,%5,%6,%7}, {%8,%9}, {%0,%1,%2,%3};"
        : "+f"(d[0]), "+f"(d[1]), "+f"(d[2]), "+f"(d[3])
        : "r"(a[0]), "r"(a[1]), "r"(a[2]), "r"(a[3]), "r"(b[0]), "r"(b[1]));
}

// stage one 64-wide K chunk of both tiles into buffer buf via cp.async
__device__ __forceinline__ void stage_chunk(uint32_t sbase, int buf, int kc,
                                            int tid, int bx, int by) {
    const __nv_bfloat16* A = gA + (size_t)bx * 128 * K2 + kc * 64;
    const __nv_bfloat16* B = gB + (size_t)by * 128 * K2 + kc * 64;
    uint32_t sb = sbase + buf * 32768;
    #pragma unroll
    for (int t = 0; t < 8; t++) {
        int i   = tid + t * 256;       // 0..2047
        int m   = t >> 2;              // 0 = A, 1 = B
        int rem = i & 1023;
        int r   = rem >> 3;            // row 0..127
        int c   = rem & 7;             // 16B seg within 128B chunk row
        const __nv_bfloat16* g = (m ? B : A) + (size_t)r * K2 + c * 8;
        uint32_t sa = sb + m * 16384 + r * 128 + ((c ^ (r & 7)) << 4);
        asm volatile("cp.async.cg.shared.global [%0], [%1], 16;" :: "r"(sa), "l"(g));
    }
    asm volatile("cp.async.commit_group;" ::: "memory");
}

// ---------------- normalize + transpose + hi/lo split (+ gS zero) --------------
__global__ void norm_kernel(const float* __restrict__ src, int which) {
    __shared__ float tile[CDIM][33];
    __shared__ float part[8][32];
    __shared__ float inv[32];

    __nv_bfloat16* dst = which ? gB : gA;   // 1 = target, 0 = input
    const int tx = threadIdx.x, ty = threadIdx.y;
    const int tid = ty * 32 + tx;

    if (which == 0 && tid < 128)            // fold gS zeroing into this launch
        gS[blockIdx.x * 128 + tid] = 0.0f;

    const int p0 = blockIdx.x * 32;
    const int b  = p0 >> 12;
    const int hw = p0 & 4095;

    const float* base = src + (size_t)b * CHW + hw + tx;
    float ps = 0.0f;
    #pragma unroll
    for (int c = ty; c < CDIM; c += 8) {
        float v = base[c * HW];
        tile[c][tx] = v;
        ps += v * v;
    }
    part[ty][tx] = ps;
    __syncthreads();
    if (ty == 0) {
        float s = 0.0f;
        #pragma unroll
        for (int i = 0; i < 8; i++) s += part[i][tx];
        inv[tx] = rsqrtf(fmaxf(s, 1e-24f));
    }
    __syncthreads();

    #pragma unroll
    for (int idx = tid; idx < 32 * CDIM; idx += 256) {
        int pix = idx >> 7;
        int c   = idx & 127;
        float v = tile[c][pix] * inv[pix];
        __nv_bfloat16 h = __float2bfloat16(v);
        __nv_bfloat16 l = __float2bfloat16(v - __bfloat162float(h));
        size_t o = (size_t)(p0 + pix) * K2 + c;
        dst[o] = h;
        dst[o + CDIM] = l;
    }
}

// ---------------- pipelined HMMA GEMM + register epilogue ----------------------
// D[b, a] = input_row(b) . target_row(a) over K=256; rows=input, cols=target
__global__ __launch_bounds__(256, 2)
void gemm_kernel(const int* __restrict__ tseg) {
    extern __shared__ char smem[];
    int*   cls  = (int*)(smem + SM_CLS);
    float* sRed = (float*)(smem + SM_RED);      // [4][128]

    const int tid  = threadIdx.x;
    const int wid  = tid >> 5;
    const int lane = tid & 31;
    const int bx = blockIdx.x, by = blockIdx.y;
    const uint32_t sbase = smem_u32(smem);

    if (tid < 128) cls[tid] = tseg[by * 128 + tid];
    sRed[tid] = 0.0f;
    sRed[tid + 256] = 0.0f;

    stage_chunk(sbase, 0, 0, tid, bx, by);
    stage_chunk(sbase, 1, 1, tid, bx, by);

    const int wm = wid >> 2;            // 0..1
    const int wn = wid & 3;             // 0..3
    const int ar = wm * 64 + (lane & 15);
    const int ah = lane >> 4;
    const int bc = wn * 32 + (lane & 7) + ((lane >> 4) << 3);
    const int bh = (lane >> 3) & 1;

    uint32_t aoff[4]; int arx[4];
    #pragma unroll
    for (int mt = 0; mt < 4; mt++) {
        int r = ar + mt * 16;
        aoff[mt] = r * 128;
        arx[mt]  = r & 7;
    }
    uint32_t boff[2]; int bcx[2];
    #pragma unroll
    for (int p = 0; p < 2; p++) {
        int c0 = bc + p * 16;
        boff[p] = 16384 + c0 * 128;
        bcx[p]  = c0 & 7;
    }

    float acc[4][4][4];
    #pragma unroll
    for (int mt = 0; mt < 4; mt++)
        #pragma unroll
        for (int nt = 0; nt < 4; nt++)
            #pragma unroll
            for (int q = 0; q < 4; q++) acc[mt][nt][q] = 0.0f;

    #pragma unroll
    for (int kc = 0; kc < 4; kc++) {
        if (kc < 3) asm volatile("cp.async.wait_group 1;" ::: "memory");
        else        asm volatile("cp.async.wait_group 0;" ::: "memory");
        __syncthreads();

        const uint32_t bb = sbase + (kc & 1) * 32768;
        #pragma unroll
        for (int kkl = 0; kkl < 4; kkl++) {
            uint32_t a[4][4], b[4][2];
            const int ca = kkl * 2 + ah;
            #pragma unroll
            for (int mt = 0; mt < 4; mt++)
                ldsm_x4(a[mt][0], a[mt][1], a[mt][2], a[mt][3],
                        bb + aoff[mt] + ((ca ^ arx[mt]) << 4));
            const int cb = kkl * 2 + bh;
            #pragma unroll
            for (int p = 0; p < 2; p++)
                ldsm_x4(b[2 * p][0], b[2 * p][1], b[2 * p + 1][0], b[2 * p + 1][1],
                        bb + boff[p] + ((cb ^ bcx[p]) << 4));
            #pragma unroll
            for (int mt = 0; mt < 4; mt++)
                #pragma unroll
                for (int nt = 0; nt < 4; nt++)
                    mma16816(acc[mt][nt], a[mt], b[nt]);
        }
        __syncthreads();
        if (kc < 2) stage_chunk(sbase, kc & 1, kc + 2, tid, bx, by);
    }

    // ---- register epilogue: exp + per-class row sums, quad-reduced -----------
    int cr[8];
    #pragma unroll
    for (int nt = 0; nt < 4; nt++)
        #pragma unroll
        for (int j = 0; j < 2; j++)
            cr[nt * 2 + j] = cls[wn * 32 + nt * 8 + (lane & 3) * 2 + j];

    #pragma unroll
    for (int mt = 0; mt < 4; mt++) {
        #pragma unroll
        for (int h = 0; h < 2; h++) {
            float s0 = 0.f, s1 = 0.f, s2 = 0.f, s3 = 0.f;
            #pragma unroll
            for (int nt = 0; nt < 4; nt++) {
                #pragma unroll
                for (int j = 0; j < 2; j++) {
                    float e = __expf(acc[mt][nt][h * 2 + j] * INV_TAU);
                    int k = cr[nt * 2 + j];
                    s0 += (k == 0) ? e : 0.f;
                    s1 += (k == 1) ? e : 0.f;
                    s2 += (k == 2) ? e : 0.f;
                    s3 += (k == 3) ? e : 0.f;
                }
            }
            s0 += __shfl_xor_sync(0xffffffffu, s0, 1);
            s0 += __shfl_xor_sync(0xffffffffu, s0, 2);
            s1 += __shfl_xor_sync(0xffffffffu, s1, 1);
            s1 += __shfl_xor_sync(0xffffffffu, s1, 2);
            s2 += __shfl_xor_sync(0xffffffffu, s2, 1);
            s2 += __shfl_xor_sync(0xffffffffu, s2, 2);
            s3 += __shfl_xor_sync(0xffffffffu, s3, 1);
            s3 += __shfl_xor_sync(0xffffffffu, s3, 2);
            if ((lane & 3) == 0) {
                int r = wm * 64 + mt * 16 + (lane >> 2) + h * 8;
                atomicAdd(&sRed[0 * 128 + r], s0);
                atomicAdd(&sRed[1 * 128 + r], s1);
                atomicAdd(&sRed[2 * 128 + r], s2);
                atomicAdd(&sRed[3 * 128 + r], s3);
            }
        }
    }
    __syncthreads();

    #pragma unroll
    for (int t = 0; t < 2; t++) {
        int i = tid + t * 256;
        atomicAdd(&gS[(i >> 7) * NPIX + bx * 128 + (i & 127)], sRed[i]);
    }
}

// ---------------- final loss ---------------------------------------------------
__global__ void loss_part_kernel(const int* __restrict__ piSeg) {
    __shared__ float red[256];
    const int b = blockIdx.x * 256 + threadIdx.x;
    int p = piSeg[b];
    float nom = gS[p * NPIX + b];
    float den = gS[b] + gS[NPIX + b] + gS[2 * NPIX + b] + gS[3 * NPIX + b];
    red[threadIdx.x] = -logf(nom / (den + 1e-8f));
    __syncthreads();
    for (int s = 128; s > 0; s >>= 1) {
        if (threadIdx.x < s) red[threadIdx.x] += red[threadIdx.x + s];
        __syncthreads();
    }
    if (threadIdx.x == 0) gPartial[blockIdx.x] = red[0];
}

__global__ void loss_final_kernel(float* __restrict__ out) {
    float v = gPartial[threadIdx.x];
    #pragma unroll
    for (int o = 16; o; o >>= 1) v += __shfl_down_sync(0xffffffffu, v, o);
    if (threadIdx.x == 0) out[0] = v * (1.0f / (float)NPIX);
}

// ---------------- launch -------------------------------------------------------
extern "C" void kernel_launch(void* const* d_in, const int* in_sizes, int n_in,
                              void* d_out, int out_size) {
    const float* input  = (const float*)d_in[0];
    const float* target = (const float*)d_in[1];
    const int*   iseg   = (const int*)d_in[2];
    const int*   tseg   = (const int*)d_in[3];
    float* out = (float*)d_out;

    cudaFuncSetAttribute(gemm_kernel, cudaFuncAttributeMaxDynamicSharedMemorySize, SM_TOTAL);

    dim3 nb(32, 8);
    norm_kernel<<<NPIX / 32, nb>>>(input, 0);    // also zeroes gS
    norm_kernel<<<NPIX / 32, nb>>>(target, 1);

    dim3 grid(NPIX / 128, NPIX / 128);
    gemm_kernel<<<grid, 256, SM_TOTAL>>>(tseg);

    loss_part_kernel<<<NPIX / 256, 256>>>(iseg);
    loss_final_kernel<<<1, 32>>>(out);
}

// round 6
// speedup vs baseline: 3.8305x; 1.0312x over previous
#include <cuda_runtime.h>
#include <cuda_bf16.h>
#include <cstdint>
#include <math.h>

// Problem constants (B=2, C=128, H=64, W=64)
#define NPIX 8192
#define CDIM 128
#define HW   4096
#define CHW  524288
#define NCLS 4
#define K2   256          // stored K: [hi(128) | lo(128)] bf16
#define INV_TAU 14.285714285714286f

// ---------------- scratch (device globals; no allocation allowed) -------------
__device__ __nv_bfloat16 gA[NPIX * K2];  // input rows  [hi|lo]  (rows of D)
__device__ __nv_bfloat16 gB[NPIX * K2];  // target rows [hi|lo]  (cols of D)
__device__ float gS[NCLS * NPIX];        // per-class sums of exp(sim/tau) per input pixel
__device__ float gPartial[32];

// dynamic smem: 3 stages x 32KB {A 16K | B 16K}, then cls, then sRed
#define SM_STAGE 32768
#define SM_CLS   98304
#define SM_RED   98816
#define SM_TOTAL (98816 + 2048)

// ---------------- helpers -----------------------------------------------------
__device__ __forceinline__ uint32_t smem_u32(const void* p) {
    uint32_t a;
    asm("{ .reg .u64 t; cvta.to.shared.u64 t, %1; cvt.u32.u64 %0, t; }"
        : "=r"(a) : "l"(p));
    return a;
}

__device__ __forceinline__ void ldsm_x4(uint32_t& r0, uint32_t& r1, uint32_t& r2,
                                        uint32_t& r3, uint32_t a) {
    asm volatile("ldmatrix.sync.aligned.m8n8.x4.shared.b16 {%0,%1,%2,%3}, [%4];"
                 : "=r"(r0), "=r"(r1), "=r"(r2), "=r"(r3) : "r"(a));
}

__device__ __forceinline__ void mma16816(float* d, const uint32_t* a, const uint32_t* b) {
    asm volatile(
        "mma.sync.aligned.m16n8k16.row.col.f32.bf16.bf16.f32 "
        "{%0,%1,%2,%3}, {%4,%5,%6,%7}, {%8,%9}, {%0,%1,%2,%3};"
        : "+f"(d[0]), "+f"(d[1]), "+f"(d[2]), "+f"(d[3])
        : "r"(a[0]), "r"(a[1]), "r"(a[2]), "r"(a[3]), "r"(b[0]), "r"(b[1]));
}

// stage one 64-wide K chunk of both tiles into ring slot via cp.async
__device__ __forceinline__ void stage_chunk(uint32_t sbase, int slot, int kc,
                                            int tid, int bx, int by) {
    const __nv_bfloat16* Abase = gA + (size_t)bx * 128 * K2 + kc * 64;
    const __nv_bfloat16* Bbase = gB + (size_t)by * 128 * K2 + kc * 64;
    uint32_t sb = sbase + slot * SM_STAGE;
    #pragma unroll
    for (int t = 0; t < 8; t++) {
        int i    = tid + t * 256;       // 0..2047
        int m    = i >> 10;             // 0 = A, 1 = B
        int rrem = i & 1023;
        int row  = rrem >> 3;           // 0..127
        int c    = rrem & 7;            // 16B seg within 128B chunk row
        const __nv_bfloat16* g = (m ? Bbase : Abase) + (size_t)row * K2 + c * 8;
        uint32_t sa = sb + m * 16384 + row * 128 + ((c ^ (row & 7)) << 4);
        asm volatile("cp.async.cg.shared.global [%0], [%1], 16;" :: "r"(sa), "l"(g));
    }
    asm volatile("cp.async.commit_group;" ::: "memory");
}

// ---------------- normalize + transpose + hi/lo split (+ gS zero) --------------
__global__ void norm_kernel(const float* __restrict__ src, int which) {
    __shared__ float tile[CDIM][33];
    __shared__ float part[8][32];
    __shared__ float inv[32];

    __nv_bfloat16* dst = which ? gB : gA;   // 1 = target, 0 = input
    const int tx = threadIdx.x, ty = threadIdx.y;
    const int tid = ty * 32 + tx;

    if (which == 0 && tid < 128)            // fold gS zeroing into this launch
        gS[blockIdx.x * 128 + tid] = 0.0f;

    const int p0 = blockIdx.x * 32;
    const int b  = p0 >> 12;
    const int hw = p0 & 4095;

    const float* base = src + (size_t)b * CHW + hw + tx;
    float ps = 0.0f;
    #pragma unroll
    for (int c = ty; c < CDIM; c += 8) {
        float v = base[c * HW];
        tile[c][tx] = v;
        ps += v * v;
    }
    part[ty][tx] = ps;
    __syncthreads();
    if (ty == 0) {
        float s = 0.0f;
        #pragma unroll
        for (int i = 0; i < 8; i++) s += part[i][tx];
        inv[tx] = rsqrtf(fmaxf(s, 1e-24f));
    }
    __syncthreads();

    #pragma unroll
    for (int idx = tid; idx < 32 * CDIM; idx += 256) {
        int pix = idx >> 7;
        int c   = idx & 127;
        float v = tile[c][pix] * inv[pix];
        __nv_bfloat16 h = __float2bfloat16(v);
        __nv_bfloat16 l = __float2bfloat16(v - __bfloat162float(h));
        size_t o = (size_t)(p0 + pix) * K2 + c;
        dst[o] = h;
        dst[o + CDIM] = l;
    }
}

// ---------------- pipelined HMMA GEMM + register epilogue ----------------------
// D[b, a] = input_row(b) . target_row(a) over K=256; rows=input, cols=target
__global__ __launch_bounds__(256, 2)
void gemm_kernel(const int* __restrict__ tseg) {
    extern __shared__ char smem[];
    int*   cls  = (int*)(smem + SM_CLS);
    float* sRed = (float*)(smem + SM_RED);      // [4][128]

    const int tid  = threadIdx.x;
    const int wid  = tid >> 5;
    const int lane = tid & 31;
    const int bx = blockIdx.x, by = blockIdx.y;
    const uint32_t sbase = smem_u32(smem);

    if (tid < 128) cls[tid] = tseg[by * 128 + tid];
    sRed[tid] = 0.0f;
    sRed[tid + 256] = 0.0f;

    stage_chunk(sbase, 0, 0, tid, bx, by);
    stage_chunk(sbase, 1, 1, tid, bx, by);

    const int wm = wid >> 2;            // 0..1
    const int wn = wid & 3;             // 0..3
    const int ar = wm * 64 + (lane & 15);
    const int ah = lane >> 4;
    const int bc = wn * 32 + (lane & 7) + ((lane >> 4) << 3);
    const int bh = (lane >> 3) & 1;

    uint32_t aoff[4]; int arx[4];
    #pragma unroll
    for (int mt = 0; mt < 4; mt++) {
        int r = ar + mt * 16;
        aoff[mt] = r * 128;
        arx[mt]  = r & 7;
    }
    uint32_t boff[2]; int bcx[2];
    #pragma unroll
    for (int p = 0; p < 2; p++) {
        int c0 = bc + p * 16;
        boff[p] = 16384 + c0 * 128;
        bcx[p]  = c0 & 7;
    }

    float acc[4][4][4];
    #pragma unroll
    for (int mt = 0; mt < 4; mt++)
        #pragma unroll
        for (int nt = 0; nt < 4; nt++)
            #pragma unroll
            for (int q = 0; q < 4; q++) acc[mt][nt][q] = 0.0f;

    uint32_t a[2][4][4], b[2][4][2];

    #pragma unroll
    for (int kc = 0; kc < 4; kc++) {
        if (kc < 3) asm volatile("cp.async.wait_group 1;" ::: "memory");
        else        asm volatile("cp.async.wait_group 0;" ::: "memory");
        __syncthreads();   // single barrier per chunk (3-stage ring safety)

        const uint32_t bb = sbase + (kc % 3) * SM_STAGE;

        // prefetch k-step 0 fragments
        {
            const int ca = ah;           // kkl = 0
            #pragma unroll
            for (int mt = 0; mt < 4; mt++)
                ldsm_x4(a[0][mt][0], a[0][mt][1], a[0][mt][2], a[0][mt][3],
                        bb + aoff[mt] + ((ca ^ arx[mt]) << 4));
            const int cb = bh;
            #pragma unroll
            for (int p = 0; p < 2; p++)
                ldsm_x4(b[0][2 * p][0], b[0][2 * p][1], b[0][2 * p + 1][0],
                        b[0][2 * p + 1][1], bb + boff[p] + ((cb ^ bcx[p]) << 4));
        }

        #pragma unroll
        for (int kkl = 0; kkl < 4; kkl++) {
            const int cur = kkl & 1;
            if (kkl < 3) {
                const int nxt = cur ^ 1;
                const int ca = (kkl + 1) * 2 + ah;
                #pragma unroll
                for (int mt = 0; mt < 4; mt++)
                    ldsm_x4(a[nxt][mt][0], a[nxt][mt][1], a[nxt][mt][2], a[nxt][mt][3],
                            bb + aoff[mt] + ((ca ^ arx[mt]) << 4));
                const int cb = (kkl + 1) * 2 + bh;
                #pragma unroll
                for (int p = 0; p < 2; p++)
                    ldsm_x4(b[nxt][2 * p][0], b[nxt][2 * p][1], b[nxt][2 * p + 1][0],
                            b[nxt][2 * p + 1][1], bb + boff[p] + ((cb ^ bcx[p]) << 4));
            }
            #pragma unroll
            for (int mt = 0; mt < 4; mt++)
                #pragma unroll
                for (int nt = 0; nt < 4; nt++)
                    mma16816(acc[mt][nt], a[cur][mt], b[cur][nt]);
        }

        if (kc < 2) stage_chunk(sbase, (kc + 2) % 3, kc + 2, tid, bx, by);
    }

    // ---- register epilogue: exp + per-class row sums, quad-reduced -----------
    int cr[8];
    #pragma unroll
    for (int nt = 0; nt < 4; nt++)
        #pragma unroll
        for (int j = 0; j < 2; j++)
            cr[nt * 2 + j] = cls[wn * 32 + nt * 8 + (lane & 3) * 2 + j];

    #pragma unroll
    for (int mt = 0; mt < 4; mt++) {
        #pragma unroll
        for (int h = 0; h < 2; h++) {
            float s0 = 0.f, s1 = 0.f, s2 = 0.f, s3 = 0.f;
            #pragma unroll
            for (int nt = 0; nt < 4; nt++) {
                #pragma unroll
                for (int j = 0; j < 2; j++) {
                    float e = __expf(acc[mt][nt][h * 2 + j] * INV_TAU);
                    int k = cr[nt * 2 + j];
                    s0 += (k == 0) ? e : 0.f;
                    s1 += (k == 1) ? e : 0.f;
                    s2 += (k == 2) ? e : 0.f;
                    s3 += (k == 3) ? e : 0.f;
                }
            }
            s0 += __shfl_xor_sync(0xffffffffu, s0, 1);
            s0 += __shfl_xor_sync(0xffffffffu, s0, 2);
            s1 += __shfl_xor_sync(0xffffffffu, s1, 1);
            s1 += __shfl_xor_sync(0xffffffffu, s1, 2);
            s2 += __shfl_xor_sync(0xffffffffu, s2, 1);
            s2 += __shfl_xor_sync(0xffffffffu, s2, 2);
            s3 += __shfl_xor_sync(0xffffffffu, s3, 1);
            s3 += __shfl_xor_sync(0xffffffffu, s3, 2);
            if ((lane & 3) == 0) {
                int r = wm * 64 + mt * 16 + (lane >> 2) + h * 8;
                atomicAdd(&sRed[0 * 128 + r], s0);
                atomicAdd(&sRed[1 * 128 + r], s1);
                atomicAdd(&sRed[2 * 128 + r], s2);
                atomicAdd(&sRed[3 * 128 + r], s3);
            }
        }
    }
    __syncthreads();

    #pragma unroll
    for (int t = 0; t < 2; t++) {
        int i = tid + t * 256;
        atomicAdd(&gS[(i >> 7) * NPIX + bx * 128 + (i & 127)], sRed[i]);
    }
}

// ---------------- final loss ---------------------------------------------------
__global__ void loss_part_kernel(const int* __restrict__ piSeg) {
    __shared__ float red[256];
    const int b = blockIdx.x * 256 + threadIdx.x;
    int p = piSeg[b];
    float nom = gS[p * NPIX + b];
    float den = gS[b] + gS[NPIX + b] + gS[2 * NPIX + b] + gS[3 * NPIX + b];
    red[threadIdx.x] = -logf(nom / (den + 1e-8f));
    __syncthreads();
    for (int s = 128; s > 0; s >>= 1) {
        if (threadIdx.x < s) red[threadIdx.x] += red[threadIdx.x + s];
        __syncthreads();
    }
    if (threadIdx.x == 0) gPartial[blockIdx.x] = red[0];
}

__global__ void loss_final_kernel(float* __restrict__ out) {
    float v = gPartial[threadIdx.x];
    #pragma unroll
    for (int o = 16; o; o >>= 1) v += __shfl_down_sync(0xffffffffu, v, o);
    if (threadIdx.x == 0) out[0] = v * (1.0f / (float)NPIX);
}

// ---------------- launch -------------------------------------------------------
extern "C" void kernel_launch(void* const* d_in, const int* in_sizes, int n_in,
                              void* d_out, int out_size) {
    const float* input  = (const float*)d_in[0];
    const float* target = (const float*)d_in[1];
    const int*   iseg   = (const int*)d_in[2];
    const int*   tseg   = (const int*)d_in[3];
    float* out = (float*)d_out;

    cudaFuncSetAttribute(gemm_kernel, cudaFuncAttributeMaxDynamicSharedMemorySize, SM_TOTAL);

    dim3 nb(32, 8);
    norm_kernel<<<NPIX / 32, nb>>>(input, 0);    // also zeroes gS
    norm_kernel<<<NPIX / 32, nb>>>(target, 1);

    dim3 grid(NPIX / 128, NPIX / 128);
    gemm_kernel<<<grid, 256, SM_TOTAL>>>(tseg);

    loss_part_kernel<<<NPIX / 256, 256>>>(iseg);
    loss_final_kernel<<<1, 32>>>(out);
}

// round 7
// speedup vs baseline: 4.6124x; 1.2041x over previous
#include <cuda_runtime.h>
#include <cuda_bf16.h>
#include <cstdint>
#include <math.h>

// Problem constants (B=2, C=128, H=64, W=64)
#define NPIX 8192
#define CDIM 128
#define HW   4096
#define CHW  524288
#define NCLS 4
#define INV_TAU 14.285714285714286f

// ---------------- scratch (device globals; no allocation allowed) -------------
__device__ __nv_bfloat16 gA[NPIX * CDIM];  // input rows (hi only)  -> rows of D
__device__ __nv_bfloat16 gB[NPIX * CDIM];  // target rows (hi only) -> cols of D
__device__ float gS[NCLS * NPIX];          // per-class sums of exp(sim/tau)
__device__ float gPartial[32];

// dynamic smem: 2 stages x 32KB {A 16K | B 16K}, then cls, then sRed
#define SM_STAGE 32768
#define SM_CLS   65536
#define SM_RED   66048
#define SM_TOTAL (66048 + 2048)

// ---------------- helpers -----------------------------------------------------
__device__ __forceinline__ uint32_t smem_u32(const void* p) {
    uint32_t a;
    asm("{ .reg .u64 t; cvta.to.shared.u64 t, %1; cvt.u32.u64 %0, t; }"
        : "=r"(a) : "l"(p));
    return a;
}

__device__ __forceinline__ void ldsm_x4(uint32_t& r0, uint32_t& r1, uint32_t& r2,
                                        uint32_t& r3, uint32_t a) {
    asm volatile("ldmatrix.sync.aligned.m8n8.x4.shared.b16 {%0,%1,%2,%3}, [%4];"
                 : "=r"(r0), "=r"(r1), "=r"(r2), "=r"(r3) : "r"(a));
}

__device__ __forceinline__ void mma16816(float* d, const uint32_t* a, const uint32_t* b) {
    asm volatile(
        "mma.sync.aligned.m16n8k16.row.col.f32.bf16.bf16.f32 "
        "{%0,%1,%2,%3}, {%4,%5,%6,%7}, {%8,%9}, {%0,%1,%2,%3};"
        : "+f"(d[0]), "+f"(d[1]), "+f"(d[2]), "+f"(d[3])
        : "r"(a[0]), "r"(a[1]), "r"(a[2]), "r"(a[3]), "r"(b[0]), "r"(b[1]));
}

// stage one 64-wide K chunk of both tiles into slot via cp.async (16 KB + 16 KB)
__device__ __forceinline__ void stage_chunk(uint32_t sbase, int slot, int kc,
                                            int tid, int bx, int by) {
    const __nv_bfloat16* Abase = gA + (size_t)bx * 128 * CDIM + kc * 64;
    const __nv_bfloat16* Bbase = gB + (size_t)by * 128 * CDIM + kc * 64;
    uint32_t sb = sbase + slot * SM_STAGE;
    #pragma unroll
    for (int t = 0; t < 8; t++) {
        int i    = tid + t * 256;       // 0..2047
        int m    = i >> 10;             // 0 = A, 1 = B
        int rrem = i & 1023;
        int row  = rrem >> 3;           // 0..127
        int c    = rrem & 7;            // 16B seg within 128B chunk row
        const __nv_bfloat16* g = (m ? Bbase : Abase) + (size_t)row * CDIM + c * 8;
        uint32_t sa = sb + m * 16384 + row * 128 + ((c ^ (row & 7)) << 4);
        asm volatile("cp.async.cg.shared.global [%0], [%1], 16;" :: "r"(sa), "l"(g));
    }
    asm volatile("cp.async.commit_group;" ::: "memory");
}

// ---------------- normalize + transpose -> bf16 (+ gS zero) --------------------
__global__ void norm_kernel(const float* __restrict__ src, int which) {
    __shared__ float tile[CDIM][33];
    __shared__ float part[8][32];
    __shared__ float inv[32];

    __nv_bfloat16* dst = which ? gB : gA;   // 1 = target, 0 = input
    const int tx = threadIdx.x, ty = threadIdx.y;
    const int tid = ty * 32 + tx;

    if (which == 0 && tid < 128)            // fold gS zeroing into this launch
        gS[blockIdx.x * 128 + tid] = 0.0f;

    const int p0 = blockIdx.x * 32;
    const int b  = p0 >> 12;
    const int hw = p0 & 4095;

    const float* base = src + (size_t)b * CHW + hw + tx;
    float ps = 0.0f;
    #pragma unroll
    for (int c = ty; c < CDIM; c += 8) {
        float v = base[c * HW];
        tile[c][tx] = v;
        ps += v * v;
    }
    part[ty][tx] = ps;
    __syncthreads();
    if (ty == 0) {
        float s = 0.0f;
        #pragma unroll
        for (int i = 0; i < 8; i++) s += part[i][tx];
        inv[tx] = rsqrtf(fmaxf(s, 1e-24f));
    }
    __syncthreads();

    #pragma unroll
    for (int idx = tid; idx < 32 * CDIM; idx += 256) {
        int pix = idx >> 7;
        int c   = idx & 127;
        dst[(size_t)(p0 + pix) * CDIM + c] =
            __float2bfloat16(tile[c][pix] * inv[pix]);
    }
}

// ---------------- pipelined HMMA GEMM + register epilogue ----------------------
// D[b, a] = input_row(b) . target_row(a) over K=128; rows=input, cols=target
__global__ __launch_bounds__(256, 2)
void gemm_kernel(const int* __restrict__ tseg) {
    extern __shared__ char smem[];
    int*   cls  = (int*)(smem + SM_CLS);
    float* sRed = (float*)(smem + SM_RED);      // [4][128]

    const int tid  = threadIdx.x;
    const int wid  = tid >> 5;
    const int lane = tid & 31;
    const int bx = blockIdx.x, by = blockIdx.y;
    const uint32_t sbase = smem_u32(smem);

    if (tid < 128) cls[tid] = tseg[by * 128 + tid];
    sRed[tid] = 0.0f;
    sRed[tid + 256] = 0.0f;

    stage_chunk(sbase, 0, 0, tid, bx, by);
    stage_chunk(sbase, 1, 1, tid, bx, by);

    const int wm = wid >> 2;            // 0..1
    const int wn = wid & 3;             // 0..3
    const int ar = wm * 64 + (lane & 15);
    const int ah = lane >> 4;
    const int bc = wn * 32 + (lane & 7) + ((lane >> 4) << 3);
    const int bh = (lane >> 3) & 1;

    uint32_t aoff[4]; int arx[4];
    #pragma unroll
    for (int mt = 0; mt < 4; mt++) {
        int r = ar + mt * 16;
        aoff[mt] = r * 128;
        arx[mt]  = r & 7;
    }
    uint32_t boff[2]; int bcx[2];
    #pragma unroll
    for (int p = 0; p < 2; p++) {
        int c0 = bc + p * 16;
        boff[p] = 16384 + c0 * 128;
        bcx[p]  = c0 & 7;
    }

    float acc[4][4][4];
    #pragma unroll
    for (int mt = 0; mt < 4; mt++)
        #pragma unroll
        for (int nt = 0; nt < 4; nt++)
            #pragma unroll
            for (int q = 0; q < 4; q++) acc[mt][nt][q] = 0.0f;

    uint32_t a[2][4][4], b[2][4][2];

    #pragma unroll
    for (int kc = 0; kc < 2; kc++) {
        if (kc == 0) asm volatile("cp.async.wait_group 1;" ::: "memory");
        else         asm volatile("cp.async.wait_group 0;" ::: "memory");
        __syncthreads();

        const uint32_t bb = sbase + kc * SM_STAGE;

        // prefetch k-step 0 fragments
        {
            const int ca = ah;
            #pragma unroll
            for (int mt = 0; mt < 4; mt++)
                ldsm_x4(a[0][mt][0], a[0][mt][1], a[0][mt][2], a[0][mt][3],
                        bb + aoff[mt] + ((ca ^ arx[mt]) << 4));
            const int cb = bh;
            #pragma unroll
            for (int p = 0; p < 2; p++)
                ldsm_x4(b[0][2 * p][0], b[0][2 * p][1], b[0][2 * p + 1][0],
                        b[0][2 * p + 1][1], bb + boff[p] + ((cb ^ bcx[p]) << 4));
        }

        #pragma unroll
        for (int kkl = 0; kkl < 4; kkl++) {
            const int cur = kkl & 1;
            if (kkl < 3) {
                const int nxt = cur ^ 1;
                const int ca = (kkl + 1) * 2 + ah;
                #pragma unroll
                for (int mt = 0; mt < 4; mt++)
                    ldsm_x4(a[nxt][mt][0], a[nxt][mt][1], a[nxt][mt][2], a[nxt][mt][3],
                            bb + aoff[mt] + ((ca ^ arx[mt]) << 4));
                const int cb = (kkl + 1) * 2 + bh;
                #pragma unroll
                for (int p = 0; p < 2; p++)
                    ldsm_x4(b[nxt][2 * p][0], b[nxt][2 * p][1], b[nxt][2 * p + 1][0],
                            b[nxt][2 * p + 1][1], bb + boff[p] + ((cb ^ bcx[p]) << 4));
            }
            #pragma unroll
            for (int mt = 0; mt < 4; mt++)
                #pragma unroll
                for (int nt = 0; nt < 4; nt++)
                    mma16816(acc[mt][nt], a[cur][mt], b[cur][nt]);
        }
    }

    // ---- register epilogue: exp + per-class row sums, quad-reduced -----------
    int cr[8];
    #pragma unroll
    for (int nt = 0; nt < 4; nt++)
        #pragma unroll
        for (int j = 0; j < 2; j++)
            cr[nt * 2 + j] = cls[wn * 32 + nt * 8 + (lane & 3) * 2 + j];

    #pragma unroll
    for (int mt = 0; mt < 4; mt++) {
        #pragma unroll
        for (int h = 0; h < 2; h++) {
            float s0 = 0.f, s1 = 0.f, s2 = 0.f, s3 = 0.f;
            #pragma unroll
            for (int nt = 0; nt < 4; nt++) {
                #pragma unroll
                for (int j = 0; j < 2; j++) {
                    float e = __expf(acc[mt][nt][h * 2 + j] * INV_TAU);
                    int k = cr[nt * 2 + j];
                    s0 += (k == 0) ? e : 0.f;
                    s1 += (k == 1) ? e : 0.f;
                    s2 += (k == 2) ? e : 0.f;
                    s3 += (k == 3) ? e : 0.f;
                }
            }
            s0 += __shfl_xor_sync(0xffffffffu, s0, 1);
            s0 += __shfl_xor_sync(0xffffffffu, s0, 2);
            s1 += __shfl_xor_sync(0xffffffffu, s1, 1);
            s1 += __shfl_xor_sync(0xffffffffu, s1, 2);
            s2 += __shfl_xor_sync(0xffffffffu, s2, 1);
            s2 += __shfl_xor_sync(0xffffffffu, s2, 2);
            s3 += __shfl_xor_sync(0xffffffffu, s3, 1);
            s3 += __shfl_xor_sync(0xffffffffu, s3, 2);
            if ((lane & 3) == 0) {
                int r = wm * 64 + mt * 16 + (lane >> 2) + h * 8;
                atomicAdd(&sRed[0 * 128 + r], s0);
                atomicAdd(&sRed[1 * 128 + r], s1);
                atomicAdd(&sRed[2 * 128 + r], s2);
                atomicAdd(&sRed[3 * 128 + r], s3);
            }
        }
    }
    __syncthreads();

    #pragma unroll
    for (int t = 0; t < 2; t++) {
        int i = tid + t * 256;
        atomicAdd(&gS[(i >> 7) * NPIX + bx * 128 + (i & 127)], sRed[i]);
    }
}

// ---------------- final loss ---------------------------------------------------
__global__ void loss_part_kernel(const int* __restrict__ piSeg) {
    __shared__ float red[256];
    const int b = blockIdx.x * 256 + threadIdx.x;
    int p = piSeg[b];
    float nom = gS[p * NPIX + b];
    float den = gS[b] + gS[NPIX + b] + gS[2 * NPIX + b] + gS[3 * NPIX + b];
    red[threadIdx.x] = -logf(nom / (den + 1e-8f));
    __syncthreads();
    for (int s = 128; s > 0; s >>= 1) {
        if (threadIdx.x < s) red[threadIdx.x] += red[threadIdx.x + s];
        __syncthreads();
    }
    if (threadIdx.x == 0) gPartial[blockIdx.x] = red[0];
}

__global__ void loss_final_kernel(float* __restrict__ out) {
    float v = gPartial[threadIdx.x];
    #pragma unroll
    for (int o = 16; o; o >>= 1) v += __shfl_down_sync(0xffffffffu, v, o);
    if (threadIdx.x == 0) out[0] = v * (1.0f / (float)NPIX);
}

// ---------------- launch -------------------------------------------------------
extern "C" void kernel_launch(void* const* d_in, const int* in_sizes, int n_in,
                              void* d_out, int out_size) {
    const float* input  = (const float*)d_in[0];
    const float* target = (const float*)d_in[1];
    const int*   iseg   = (const int*)d_in[2];
    const int*   tseg   = (const int*)d_in[3];
    float* out = (float*)d_out;

    cudaFuncSetAttribute(gemm_kernel, cudaFuncAttributeMaxDynamicSharedMemorySize, SM_TOTAL);

    dim3 nb(32, 8);
    norm_kernel<<<NPIX / 32, nb>>>(input, 0);    // also zeroes gS
    norm_kernel<<<NPIX / 32, nb>>>(target, 1);

    dim3 grid(NPIX / 128, NPIX / 128);
    gemm_kernel<<<grid, 256, SM_TOTAL>>>(tseg);

    loss_part_kernel<<<NPIX / 256, 256>>>(iseg);
    loss_final_kernel<<<1, 32>>>(out);
}

// round 8
// speedup vs baseline: 7.2060x; 1.5623x over previous
#include <cuda_runtime.h>
#include <cuda_bf16.h>
#include <cstdint>
#include <math.h>

// Problem constants (B=2, C=128, H=64, W=64)
#define NPIX 8192
#define CDIM 128
#define HW   4096
#define CHW  524288
#define INV_TAU 14.285714285714286f

// ---------------- scratch (device globals; no allocation allowed) -------------
__device__ __nv_bfloat16 gA[NPIX * CDIM];  // input rows  -> rows of D
__device__ __nv_bfloat16 gB[NPIX * CDIM];  // target rows -> cols of D
__device__ float gS[2 * NPIX];             // [0]=total sums, [1]=match sums

// dynamic smem: 2 stages x 32KB {A 16K | B 16K}, cls_t, cls_i, sRed(float2[4][128])
#define SM_STAGE 32768
#define SM_CLS_T 65536
#define SM_CLS_I 66048
#define SM_RED   66560
#define SM_TOTAL (66560 + 4096)

// ---------------- helpers -----------------------------------------------------
__device__ __forceinline__ uint32_t smem_u32(const void* p) {
    uint32_t a;
    asm("{ .reg .u64 t; cvta.to.shared.u64 t, %1; cvt.u32.u64 %0, t; }"
        : "=r"(a) : "l"(p));
    return a;
}

__device__ __forceinline__ void ldsm_x4(uint32_t& r0, uint32_t& r1, uint32_t& r2,
                                        uint32_t& r3, uint32_t a) {
    asm volatile("ldmatrix.sync.aligned.m8n8.x4.shared.b16 {%0,%1,%2,%3}, [%4];"
                 : "=r"(r0), "=r"(r1), "=r"(r2), "=r"(r3) : "r"(a));
}

__device__ __forceinline__ void mma16816(float* d, const uint32_t* a, const uint32_t* b) {
    asm volatile(
        "mma.sync.aligned.m16n8k16.row.col.f32.bf16.bf16.f32 "
        "{%0,%1,%2,%3}, {%4,%5,%6,%7}, {%8,%9}, {%0,%1,%2,%3};"
        : "+f"(d[0]), "+f"(d[1]), "+f"(d[2]), "+f"(d[3])
        : "r"(a[0]), "r"(a[1]), "r"(a[2]), "r"(a[3]), "r"(b[0]), "r"(b[1]));
}

// stage one 64-wide K chunk of both tiles into slot via cp.async
__device__ __forceinline__ void stage_chunk(uint32_t sbase, int slot, int kc,
                                            int tid, int bx, int by) {
    const __nv_bfloat16* Abase = gA + (size_t)bx * 128 * CDIM + kc * 64;
    const __nv_bfloat16* Bbase = gB + (size_t)by * 128 * CDIM + kc * 64;
    uint32_t sb = sbase + slot * SM_STAGE;
    #pragma unroll
    for (int t = 0; t < 8; t++) {
        int i    = tid + t * 256;       // 0..2047
        int m    = i >> 10;             // 0 = A, 1 = B
        int rrem = i & 1023;
        int row  = rrem >> 3;           // 0..127
        int c    = rrem & 7;            // 16B seg within 128B chunk row
        const __nv_bfloat16* g = (m ? Bbase : Abase) + (size_t)row * CDIM + c * 8;
        uint32_t sa = sb + m * 16384 + row * 128 + ((c ^ (row & 7)) << 4);
        asm volatile("cp.async.cg.shared.global [%0], [%1], 16;" :: "r"(sa), "l"(g));
    }
    asm volatile("cp.async.commit_group;" ::: "memory");
}

// ---------------- fused normalize (both tensors) + gS zero ---------------------
__global__ void norm_kernel(const float* __restrict__ in, const float* __restrict__ tg) {
    __shared__ float tile[CDIM][33];
    __shared__ float part[8][32];
    __shared__ float inv[32];

    const int blk   = blockIdx.x;
    const int which = blk >> 8;             // 0: input, 1: target
    const int sub   = blk & 255;
    const float* src = which ? tg : in;
    __nv_bfloat16* dst = which ? gB : gA;

    const int tx = threadIdx.x, ty = threadIdx.y;
    const int tid = ty * 32 + tx;

    if (which == 0 && tid < 64)             // zero gS (256 blocks x 64 = 16384)
        gS[sub * 64 + tid] = 0.0f;

    const int p0 = sub * 32;
    const int b  = p0 >> 12;
    const int hw = p0 & 4095;

    const float* base = src + (size_t)b * CHW + hw + tx;
    float ps = 0.0f;
    #pragma unroll
    for (int c = ty; c < CDIM; c += 8) {
        float v = base[c * HW];
        tile[c][tx] = v;
        ps += v * v;
    }
    part[ty][tx] = ps;
    __syncthreads();
    if (ty == 0) {
        float s = 0.0f;
        #pragma unroll
        for (int i = 0; i < 8; i++) s += part[i][tx];
        inv[tx] = rsqrtf(fmaxf(s, 1e-24f));
    }
    __syncthreads();

    #pragma unroll
    for (int idx = tid; idx < 32 * CDIM; idx += 256) {
        int pix = idx >> 7;
        int c   = idx & 127;
        dst[(size_t)(p0 + pix) * CDIM + c] =
            __float2bfloat16(tile[c][pix] * inv[pix]);
    }
}

// ---------------- pipelined HMMA GEMM + 2-sum register epilogue ----------------
// D[b, a] = input_row(b) . target_row(a); rows=input (class pi), cols=target (pt)
__global__ __launch_bounds__(256, 2)
void gemm_kernel(const int* __restrict__ tseg, const int* __restrict__ iseg) {
    extern __shared__ char smem[];
    int*    cls_t = (int*)(smem + SM_CLS_T);
    int*    cls_i = (int*)(smem + SM_CLS_I);
    float2* sRed  = (float2*)(smem + SM_RED);    // [4 warps-n][128 rows]

    const int tid  = threadIdx.x;
    const int wid  = tid >> 5;
    const int lane = tid & 31;
    const int bx = blockIdx.x, by = blockIdx.y;
    const uint32_t sbase = smem_u32(smem);

    if (tid < 128) {
        cls_t[tid] = tseg[by * 128 + tid];
        cls_i[tid] = iseg[bx * 128 + tid];
    }

    stage_chunk(sbase, 0, 0, tid, bx, by);
    stage_chunk(sbase, 1, 1, tid, bx, by);

    const int wm = wid >> 2;            // 0..1
    const int wn = wid & 3;             // 0..3
    const int ar = wm * 64 + (lane & 15);
    const int ah = lane >> 4;
    const int bc = wn * 32 + (lane & 7) + ((lane >> 4) << 3);
    const int bh = (lane >> 3) & 1;

    uint32_t aoff[4]; int arx[4];
    #pragma unroll
    for (int mt = 0; mt < 4; mt++) {
        int r = ar + mt * 16;
        aoff[mt] = r * 128;
        arx[mt]  = r & 7;
    }
    uint32_t boff[2]; int bcx[2];
    #pragma unroll
    for (int p = 0; p < 2; p++) {
        int c0 = bc + p * 16;
        boff[p] = 16384 + c0 * 128;
        bcx[p]  = c0 & 7;
    }

    float acc[4][4][4];
    #pragma unroll
    for (int mt = 0; mt < 4; mt++)
        #pragma unroll
        for (int nt = 0; nt < 4; nt++)
            #pragma unroll
            for (int q = 0; q < 4; q++) acc[mt][nt][q] = 0.0f;

    uint32_t a[2][4][4], b[2][4][2];

    #pragma unroll
    for (int kc = 0; kc < 2; kc++) {
        if (kc == 0) asm volatile("cp.async.wait_group 1;" ::: "memory");
        else         asm volatile("cp.async.wait_group 0;" ::: "memory");
        __syncthreads();

        const uint32_t bb = sbase + kc * SM_STAGE;

        // prefetch k-step 0 fragments
        {
            const int ca = ah;
            #pragma unroll
            for (int mt = 0; mt < 4; mt++)
                ldsm_x4(a[0][mt][0], a[0][mt][1], a[0][mt][2], a[0][mt][3],
                        bb + aoff[mt] + ((ca ^ arx[mt]) << 4));
            const int cb = bh;
            #pragma unroll
            for (int p = 0; p < 2; p++)
                ldsm_x4(b[0][2 * p][0], b[0][2 * p][1], b[0][2 * p + 1][0],
                        b[0][2 * p + 1][1], bb + boff[p] + ((cb ^ bcx[p]) << 4));
        }

        #pragma unroll
        for (int kkl = 0; kkl < 4; kkl++) {
            const int cur = kkl & 1;
            if (kkl < 3) {
                const int nxt = cur ^ 1;
                const int ca = (kkl + 1) * 2 + ah;
                #pragma unroll
                for (int mt = 0; mt < 4; mt++)
                    ldsm_x4(a[nxt][mt][0], a[nxt][mt][1], a[nxt][mt][2], a[nxt][mt][3],
                            bb + aoff[mt] + ((ca ^ arx[mt]) << 4));
                const int cb = (kkl + 1) * 2 + bh;
                #pragma unroll
                for (int p = 0; p < 2; p++)
                    ldsm_x4(b[nxt][2 * p][0], b[nxt][2 * p][1], b[nxt][2 * p + 1][0],
                            b[nxt][2 * p + 1][1], bb + boff[p] + ((cb ^ bcx[p]) << 4));
            }
            #pragma unroll
            for (int mt = 0; mt < 4; mt++)
                #pragma unroll
                for (int nt = 0; nt < 4; nt++)
                    mma16816(acc[mt][nt], a[cur][mt], b[cur][nt]);
        }
    }

    // ---- 2-sum register epilogue: exp + (total, match) per row ---------------
    int cr[8];
    #pragma unroll
    for (int nt = 0; nt < 4; nt++)
        #pragma unroll
        for (int j = 0; j < 2; j++)
            cr[nt * 2 + j] = cls_t[wn * 32 + nt * 8 + (lane & 3) * 2 + j];

    #pragma unroll
    for (int mt = 0; mt < 4; mt++) {
        #pragma unroll
        for (int h = 0; h < 2; h++) {
            const int r = wm * 64 + mt * 16 + (lane >> 2) + h * 8;
            const int myk = cls_i[r];
            float tot = 0.f, mat = 0.f;
            #pragma unroll
            for (int nt = 0; nt < 4; nt++) {
                #pragma unroll
                for (int j = 0; j < 2; j++) {
                    float e = __expf(acc[mt][nt][h * 2 + j] * INV_TAU);
                    tot += e;
                    mat += (cr[nt * 2 + j] == myk) ? e : 0.f;
                }
            }
            tot += __shfl_xor_sync(0xffffffffu, tot, 1);
            tot += __shfl_xor_sync(0xffffffffu, tot, 2);
            mat += __shfl_xor_sync(0xffffffffu, mat, 1);
            mat += __shfl_xor_sync(0xffffffffu, mat, 2);
            if ((lane & 3) == 0)
                sRed[wn * 128 + r] = make_float2(tot, mat);
        }
    }
    __syncthreads();

    if (tid < 128) {
        float t = 0.f, m = 0.f;
        #pragma unroll
        for (int w = 0; w < 4; w++) {
            float2 v = sRed[w * 128 + tid];
            t += v.x;
            m += v.y;
        }
        int bg = bx * 128 + tid;
        atomicAdd(&gS[bg], t);
        atomicAdd(&gS[NPIX + bg], m);
    }
}

// ---------------- final loss (single block) ------------------------------------
__global__ void loss_kernel(float* __restrict__ out) {
    __shared__ float red[1024];
    float s = 0.0f;
    for (int b = threadIdx.x; b < NPIX; b += 1024) {
        float den = gS[b];
        float nom = gS[NPIX + b];
        s += -logf(nom / (den + 1e-8f));
    }
    red[threadIdx.x] = s;
    __syncthreads();
    for (int st = 512; st > 0; st >>= 1) {
        if (threadIdx.x < st) red[threadIdx.x] += red[threadIdx.x + st];
        __syncthreads();
    }
    if (threadIdx.x == 0) out[0] = red[0] * (1.0f / (float)NPIX);
}

// ---------------- launch -------------------------------------------------------
extern "C" void kernel_launch(void* const* d_in, const int* in_sizes, int n_in,
                              void* d_out, int out_size) {
    const float* input  = (const float*)d_in[0];
    const float* target = (const float*)d_in[1];
    const int*   iseg   = (const int*)d_in[2];
    const int*   tseg   = (const int*)d_in[3];
    float* out = (float*)d_out;

    cudaFuncSetAttribute(gemm_kernel, cudaFuncAttributeMaxDynamicSharedMemorySize, SM_TOTAL);

    dim3 nb(32, 8);
    norm_kernel<<<512, nb>>>(input, target);   // both tensors + gS zero

    dim3 grid(NPIX / 128, NPIX / 128);
    gemm_kernel<<<grid, 256, SM_TOTAL>>>(tseg, iseg);

    loss_kernel<<<1, 1024>>>(out);
}

// round 9
// speedup vs baseline: 8.2123x; 1.1396x over previous
#include <cuda_runtime.h>
#include <cuda_bf16.h>
#include <cstdint>
#include <math.h>

// Problem constants (B=2, C=128, H=64, W=64)
#define NPIX 8192
#define CDIM 128
#define HW   4096
#define CHW  524288
#define EXP_SCALE 20.609929155556625f   // (1/0.07) * log2(e)

// ---------------- scratch (device globals; no allocation allowed) -------------
__device__ __nv_bfloat16 gA[NPIX * CDIM];  // input rows  -> rows of D
__device__ __nv_bfloat16 gB[NPIX * CDIM];  // target rows -> cols of D
__device__ float gS[2 * NPIX];             // [0]=total sums, [1]=match sums

// dynamic smem layout
#define SM_A     0        // 32KB: A chunks kc0 [0,16K), kc1 [16K,32K)
#define SM_B     32768    // 4 ring slots x 16KB
#define SM_CLS_T 98304    // 512 ints
#define SM_CLS_I 100352   // 128 ints
#define SM_RED   100864   // float2[4][128] = 4KB
#define SM_TOTAL 104960

// ---------------- helpers -----------------------------------------------------
__device__ __forceinline__ uint32_t smem_u32(const void* p) {
    uint32_t a;
    asm("{ .reg .u64 t; cvta.to.shared.u64 t, %1; cvt.u32.u64 %0, t; }"
        : "=r"(a) : "l"(p));
    return a;
}

__device__ __forceinline__ void ldsm_x4(uint32_t& r0, uint32_t& r1, uint32_t& r2,
                                        uint32_t& r3, uint32_t a) {
    asm volatile("ldmatrix.sync.aligned.m8n8.x4.shared.b16 {%0,%1,%2,%3}, [%4];"
                 : "=r"(r0), "=r"(r1), "=r"(r2), "=r"(r3) : "r"(a));
}

__device__ __forceinline__ void mma16816(float* d, const uint32_t* a, const uint32_t* b) {
    asm volatile(
        "mma.sync.aligned.m16n8k16.row.col.f32.bf16.bf16.f32 "
        "{%0,%1,%2,%3}, {%4,%5,%6,%7}, {%8,%9}, {%0,%1,%2,%3};"
        : "+f"(d[0]), "+f"(d[1]), "+f"(d[2]), "+f"(d[3])
        : "r"(a[0]), "r"(a[1]), "r"(a[2]), "r"(a[3]), "r"(b[0]), "r"(b[1]));
}

__device__ __forceinline__ float ex2f(float x) {
    float r;
    asm("ex2.approx.f32 %0, %1;" : "=f"(r) : "f"(x));
    return r;
}

#define CP_COMMIT() asm volatile("cp.async.commit_group;" ::: "memory")
#define CP_WAIT(n)  asm volatile("cp.async.wait_group %0;" :: "n"(n) : "memory")

// stage full A tile (128 rows x K128) into [0,32K): 8 cp.async per thread
__device__ __forceinline__ void stage_A(uint32_t sbase, int tid, int bx) {
    const __nv_bfloat16* Abase = gA + (size_t)bx * 128 * CDIM;
    #pragma unroll
    for (int t = 0; t < 8; t++) {
        int i    = tid + t * 256;        // 0..2047
        int kc   = i >> 10;              // A chunk 0/1
        int rrem = i & 1023;
        int row  = rrem >> 3;            // 0..127
        int c    = rrem & 7;             // 16B seg
        const __nv_bfloat16* g = Abase + (size_t)row * CDIM + kc * 64 + c * 8;
        uint32_t sa = sbase + kc * 16384 + row * 128 + ((c ^ (row & 7)) << 4);
        asm volatile("cp.async.cg.shared.global [%0], [%1], 16;" :: "r"(sa), "l"(g));
    }
}

// stage one B chunk (sub-tile n, k-half kc) into ring slot: 4 cp.async per thread
__device__ __forceinline__ void stage_B(uint32_t sbase, int slot, int n, int kc,
                                        int tid, int by) {
    const __nv_bfloat16* Bbase = gB + (size_t)(by * 512 + n * 128) * CDIM + kc * 64;
    uint32_t sb = sbase + SM_B + slot * 16384;
    #pragma unroll
    for (int t = 0; t < 4; t++) {
        int i   = tid + t * 256;        // 0..1023
        int row = i >> 3;               // 0..127
        int c   = i & 7;
        const __nv_bfloat16* g = Bbase + (size_t)row * CDIM + c * 8;
        uint32_t sa = sb + row * 128 + ((c ^ (row & 7)) << 4);
        asm volatile("cp.async.cg.shared.global [%0], [%1], 16;" :: "r"(sa), "l"(g));
    }
}

// ---------------- fused normalize (both tensors) + gS zero ---------------------
__global__ void norm_kernel(const float* __restrict__ in, const float* __restrict__ tg) {
    __shared__ float tile[CDIM][17];
    __shared__ float part[16][17];
    __shared__ float inv[16];

    const int blk   = blockIdx.x;
    const int which = blk >> 9;             // 0: input, 1: target
    const int sub   = blk & 511;
    const float* src = which ? tg : in;
    __nv_bfloat16* dst = which ? gB : gA;

    const int tx = threadIdx.x;             // 0..15 pixel
    const int ty = threadIdx.y;             // 0..15 channel group
    const int tid = ty * 16 + tx;

    if (which == 0 && tid < 32)             // zero gS: 512 blocks x 32 = 16384
        gS[sub * 32 + tid] = 0.0f;

    const int p0 = sub * 16;
    const int b  = p0 >> 12;
    const int hw = p0 & 4095;

    const float* base = src + (size_t)b * CHW + hw + tx;
    float ps = 0.0f;
    #pragma unroll
    for (int c = ty; c < CDIM; c += 16) {
        float v = base[c * HW];
        tile[c][tx] = v;
        ps += v * v;
    }
    part[ty][tx] = ps;
    __syncthreads();
    if (ty == 0) {
        float s = 0.0f;
        #pragma unroll
        for (int i = 0; i < 16; i++) s += part[i][tx];
        inv[tx] = rsqrtf(fmaxf(s, 1e-24f));
    }
    __syncthreads();

    #pragma unroll
    for (int idx = tid; idx < 16 * CDIM; idx += 256) {
        int pix = idx >> 7;
        int c   = idx & 127;
        dst[(size_t)(p0 + pix) * CDIM + c] =
            __float2bfloat16(tile[c][pix] * inv[pix]);
    }
}

// ---------------- 128x512 macro-tile HMMA GEMM ---------------------------------
// D[b, a] = input_row(b) . target_row(a); rows=input (pi), cols=target (pt)
// CTA: A tile 128 rows (bx), 512 target cols (by) as 4 sequential 128-sub-tiles.
__global__ __launch_bounds__(256, 2)
void gemm_kernel(const int* __restrict__ tseg, const int* __restrict__ iseg) {
    extern __shared__ char smem[];
    int*    cls_t = (int*)(smem + SM_CLS_T);     // 512 target classes
    int*    cls_i = (int*)(smem + SM_CLS_I);     // 128 input classes
    float2* sRed  = (float2*)(smem + SM_RED);    // [4 warps-n][128 rows]

    const int tid  = threadIdx.x;
    const int wid  = tid >> 5;
    const int lane = tid & 31;
    const int bx = blockIdx.x, by = blockIdx.y;
    const uint32_t sbase = smem_u32(smem);

    #pragma unroll
    for (int i = tid; i < 512; i += 256) cls_t[i] = tseg[by * 512 + i];
    if (tid < 128) cls_i[tid] = iseg[bx * 128 + tid];

    // prolog: G0 = {A full, B0}, G1 = {B1}, G2 = {B2}
    stage_A(sbase, tid, bx);
    stage_B(sbase, 0, 0, 0, tid, by); CP_COMMIT();
    stage_B(sbase, 1, 0, 1, tid, by); CP_COMMIT();
    stage_B(sbase, 2, 1, 0, tid, by); CP_COMMIT();

    const int wm = wid >> 2;            // 0..1 (64 rows each)
    const int wn = wid & 3;             // 0..3 (32 cols each)
    const int ar = wm * 64 + (lane & 15);
    const int ah = lane >> 4;
    const int bc = wn * 32 + (lane & 7) + ((lane >> 4) << 3);
    const int bh = (lane >> 3) & 1;

    uint32_t aoff[4]; int arx[4];
    #pragma unroll
    for (int mt = 0; mt < 4; mt++) {
        int r = ar + mt * 16;
        aoff[mt] = r * 128;
        arx[mt]  = r & 7;
    }
    uint32_t boff[2]; int bcx[2];
    #pragma unroll
    for (int p = 0; p < 2; p++) {
        int c0 = bc + p * 16;
        boff[p] = c0 * 128;
        bcx[p]  = c0 & 7;
    }

    float acc[4][4][4];
    #pragma unroll
    for (int mt = 0; mt < 4; mt++)
        #pragma unroll
        for (int nt = 0; nt < 4; nt++)
            #pragma unroll
            for (int q = 0; q < 4; q++) acc[mt][nt][q] = 0.0f;

    float tS[8], mS[8];                 // per (mt,h) running sums over all 512 cols
    #pragma unroll
    for (int i = 0; i < 8; i++) { tS[i] = 0.0f; mS[i] = 0.0f; }

    #pragma unroll
    for (int j = 0; j < 8; j++) {       // chunk step: sub-tile j>>1, k-half j&1
        if (j < 6)      CP_WAIT(2);
        else if (j == 6) CP_WAIT(1);
        else             CP_WAIT(0);
        __syncthreads();

        if (j < 5) {                    // prefetch B[j+3] into slot (j+3)&3
            const int jn = j + 3;
            stage_B(sbase, jn & 3, jn >> 1, jn & 1, tid, by);
            CP_COMMIT();
        }

        const uint32_t bbA = sbase + (j & 1) * 16384;
        const uint32_t bbB = sbase + SM_B + (j & 3) * 16384;

        #pragma unroll
        for (int kkl = 0; kkl < 4; kkl++) {
            uint32_t a[4][4], b[4][2];
            const int ca = kkl * 2 + ah;
            #pragma unroll
            for (int mt = 0; mt < 4; mt++)
                ldsm_x4(a[mt][0], a[mt][1], a[mt][2], a[mt][3],
                        bbA + aoff[mt] + ((ca ^ arx[mt]) << 4));
            const int cb = kkl * 2 + bh;
            #pragma unroll
            for (int p = 0; p < 2; p++)
                ldsm_x4(b[2 * p][0], b[2 * p][1], b[2 * p + 1][0],
                        b[2 * p + 1][1], bbB + boff[p] + ((cb ^ bcx[p]) << 4));
            #pragma unroll
            for (int mt = 0; mt < 4; mt++)
                #pragma unroll
                for (int nt = 0; nt < 4; nt++)
                    mma16816(acc[mt][nt], a[mt], b[nt]);
        }

        if (j & 1) {                    // sub-tile complete: fold into tS/mS
            const int n = j >> 1;
            const int* ct = cls_t + n * 128 + wn * 32 + (lane & 3) * 2;
            int cr[8];
            #pragma unroll
            for (int nt = 0; nt < 4; nt++) {
                cr[nt * 2]     = ct[nt * 8];
                cr[nt * 2 + 1] = ct[nt * 8 + 1];
            }
            #pragma unroll
            for (int mt = 0; mt < 4; mt++) {
                #pragma unroll
                for (int h = 0; h < 2; h++) {
                    const int r   = wm * 64 + mt * 16 + (lane >> 2) + h * 8;
                    const int myk = cls_i[r];
                    float tot = 0.f, mat = 0.f;
                    #pragma unroll
                    for (int nt = 0; nt < 4; nt++) {
                        #pragma unroll
                        for (int jj = 0; jj < 2; jj++) {
                            float e = ex2f(acc[mt][nt][h * 2 + jj] * EXP_SCALE);
                            tot += e;
                            mat += (cr[nt * 2 + jj] == myk) ? e : 0.f;
                        }
                    }
                    tS[mt * 2 + h] += tot;
                    mS[mt * 2 + h] += mat;
                }
            }
            #pragma unroll
            for (int mt = 0; mt < 4; mt++)
                #pragma unroll
                for (int nt = 0; nt < 4; nt++)
                    #pragma unroll
                    for (int q = 0; q < 4; q++) acc[mt][nt][q] = 0.0f;
        }
    }

    // ---- final reduce: quad shuffles once, cross-warp via smem, 2 atomics ----
    #pragma unroll
    for (int mt = 0; mt < 4; mt++) {
        #pragma unroll
        for (int h = 0; h < 2; h++) {
            float t = tS[mt * 2 + h], m = mS[mt * 2 + h];
            t += __shfl_xor_sync(0xffffffffu, t, 1);
            t += __shfl_xor_sync(0xffffffffu, t, 2);
            m += __shfl_xor_sync(0xffffffffu, m, 1);
            m += __shfl_xor_sync(0xffffffffu, m, 2);
            if ((lane & 3) == 0) {
                const int r = wm * 64 + mt * 16 + (lane >> 2) + h * 8;
                sRed[wn * 128 + r] = make_float2(t, m);
            }
        }
    }
    __syncthreads();

    if (tid < 128) {
        float t = 0.f, m = 0.f;
        #pragma unroll
        for (int w = 0; w < 4; w++) {
            float2 v = sRed[w * 128 + tid];
            t += v.x;
            m += v.y;
        }
        int bg = bx * 128 + tid;
        atomicAdd(&gS[bg], t);
        atomicAdd(&gS[NPIX + bg], m);
    }
}

// ---------------- final loss (single block) ------------------------------------
__global__ void loss_kernel(float* __restrict__ out) {
    __shared__ float red[1024];
    float s = 0.0f;
    for (int b = threadIdx.x; b < NPIX; b += 1024) {
        float den = gS[b];
        float nom = gS[NPIX + b];
        s += -__logf(nom / (den + 1e-8f));
    }
    red[threadIdx.x] = s;
    __syncthreads();
    for (int st = 512; st > 0; st >>= 1) {
        if (threadIdx.x < st) red[threadIdx.x] += red[threadIdx.x + st];
        __syncthreads();
    }
    if (threadIdx.x == 0) out[0] = red[0] * (1.0f / (float)NPIX);
}

// ---------------- launch -------------------------------------------------------
extern "C" void kernel_launch(void* const* d_in, const int* in_sizes, int n_in,
                              void* d_out, int out_size) {
    const float* input  = (const float*)d_in[0];
    const float* target = (const float*)d_in[1];
    const int*   iseg   = (const int*)d_in[2];
    const int*   tseg   = (const int*)d_in[3];
    float* out = (float*)d_out;

    cudaFuncSetAttribute(gemm_kernel, cudaFuncAttributeMaxDynamicSharedMemorySize, SM_TOTAL);

    dim3 nb(16, 16);
    norm_kernel<<<1024, nb>>>(input, target);   // both tensors + gS zero

    dim3 grid(NPIX / 128, NPIX / 512);
    gemm_kernel<<<grid, 256, SM_TOTAL>>>(tseg, iseg);

    loss_kernel<<<1, 1024>>>(out);
}